// round 16
// baseline (speedup 1.0000x reference)
#include <cuda_runtime.h>
#include <cuda_fp16.h>
#include <cstdint>

// ---------------------------------------------------------------------------
// CloudCrop R16: R15 + intra-iteration pipelining in the persistent kernel.
// Gather split into COLUMN halves matching the two K=128 GEMM rounds:
//   wait g0 -> upd cols0-127 -> round0 -> issue next g0 (cols0-127 dead)
//   wait g1 -> upd cols128-255 -> round1 (overlaps next g0 copy) -> issue g1
// Meta (lidx+rel) double-buffered via plain LDG/STS. f_gemm unchanged (R15).
// ---------------------------------------------------------------------------

#define Bc 4
#define Nc 1024
#define NS 32
#define CIN 512
#define C0 515
#define RADIUSf 0.05f
#define HMINf (-0.02f)
#define HMAXf 0.04f

#define KROWB 272             // GEMM tile row bytes (128 fp16 + 16B pad)
#define CH1 4                 // f_gemm K chunks (K=512)
#define A2ROWB 528            // A2 row bytes (256 fp16 + 16B pad)
#define FGABUF 17408          // f_gemm A tile: 64 rows * 272B
#define FGWBUF 34816          // f_gemm W tile: 128 rows * 272B
#define WBUF  69632           // tc_mlp W tile: 256 rows * 272B

// f_gemm smem
#define FG_A1    0
#define FG_W     34816
#define FG_TOTAL 104448

// tc_mlp4 smem
#define SM_A2    0            // 128 x 528 = 67584
#define SM_W     67584        // 2 x 69632 (persistent W2) -> 206848
#define SM_WR    206848       // w1rel+bias1 [256] float4 = 4096
#define SM_B2    210944       // bias2 f32 = 1024
#define SM_META  211968       // 2 x (lidx 512B + rel float4[128] 2048B) = 5120
#define MB2SZ    2560
#define SM_TOTAL 217088

// __device__ scratch (allocation-free), 16B-aligned
__device__ __align__(16) unsigned short d_fh[Bc * Nc * CIN];    // feat fp16 [p][c]
__device__ __align__(16) unsigned short d_F[Bc * Nc * 256];     // W1f·feat fp16 [p][o]
__device__ __align__(16) int            d_idx[Bc * Nc * NS];
__device__ __align__(16) float          d_rel[Bc * Nc * NS * 3];
__device__ __align__(16) unsigned short d_w1[CH1 * 256 * 128];  // [t][o][128] fp16
__device__ __align__(16) unsigned short d_w2[2 * 256 * 128];
__device__ __align__(16) float          d_wr4[256 * 4];         // {wr0,wr1,wr2,bias1}
__device__ __align__(16) float          d_bias2[256];

__device__ __forceinline__ uint32_t s2u(const void* p) {
    uint32_t a;
    asm("{ .reg .u64 t; cvta.to.shared.u64 t, %1; cvt.u32.u64 %0, t; }" : "=r"(a) : "l"(p));
    return a;
}
__device__ __forceinline__ void cpa16(uint32_t dst, const void* src) {
    asm volatile("cp.async.cg.shared.global [%0], [%1], 16;" :: "r"(dst), "l"(src));
}
#define CP_COMMIT()  asm volatile("cp.async.commit_group;" ::: "memory")
#define CP_WAITG(n)  asm volatile("cp.async.wait_group %0;" :: "n"(n) : "memory")

__device__ __forceinline__ void ldsm4(uint32_t& r0, uint32_t& r1, uint32_t& r2, uint32_t& r3,
                                      uint32_t addr) {
    asm volatile("ldmatrix.sync.aligned.m8n8.x4.shared.b16 {%0,%1,%2,%3}, [%4];"
                 : "=r"(r0), "=r"(r1), "=r"(r2), "=r"(r3) : "r"(addr));
}
#define MMA(d, A, b0r, b1r) \
    asm volatile("mma.sync.aligned.m16n8k16.row.col.f32.f16.f16.f32 " \
                 "{%0,%1,%2,%3},{%4,%5,%6,%7},{%8,%9},{%0,%1,%2,%3};" \
                 : "+f"((d).x), "+f"((d).y), "+f"((d).z), "+f"((d).w) \
                 : "r"((A)[0]), "r"((A)[1]), "r"((A)[2]), "r"((A)[3]), \
                   "r"(b0r), "r"(b1r))

// K=128 round, 64x64 warp tile
template<int AROW>
__device__ __forceinline__ void gemm_round(float4 (&acc)[4][8], uint32_t a, uint32_t wb)
{
    #pragma unroll
    for (int kk = 0; kk < 8; kk++) {
        uint32_t Ax[4][4], Bf[4][4];
        uint32_t ak = a + kk * 32, wk = wb + kk * 32;
        #pragma unroll
        for (int mt = 0; mt < 4; mt++)
            ldsm4(Ax[mt][0], Ax[mt][1], Ax[mt][2], Ax[mt][3], ak + mt * 16 * AROW);
        #pragma unroll
        for (int p = 0; p < 4; p++)
            ldsm4(Bf[p][0], Bf[p][1], Bf[p][2], Bf[p][3], wk + p * 16 * KROWB);
        #pragma unroll
        for (int mt = 0; mt < 4; mt++) {
            #pragma unroll
            for (int p = 0; p < 4; p++) {
                MMA(acc[mt][2*p],   Ax[mt], Bf[p][0], Bf[p][1]);
                MMA(acc[mt][2*p+1], Ax[mt], Bf[p][2], Bf[p][3]);
            }
        }
    }
}

// K=128 round, 32x32 warp tile (f_gemm)
__device__ __forceinline__ void gemm_round32(float4 (&acc)[2][4], uint32_t a, uint32_t wb)
{
    #pragma unroll
    for (int kk = 0; kk < 8; kk++) {
        uint32_t Ax[2][4], Bf[2][4];
        uint32_t ak = a + kk * 32, wk = wb + kk * 32;
        #pragma unroll
        for (int mt = 0; mt < 2; mt++)
            ldsm4(Ax[mt][0], Ax[mt][1], Ax[mt][2], Ax[mt][3], ak + mt * 16 * KROWB);
        #pragma unroll
        for (int p = 0; p < 2; p++)
            ldsm4(Bf[p][0], Bf[p][1], Bf[p][2], Bf[p][3], wk + p * 16 * KROWB);
        #pragma unroll
        for (int mt = 0; mt < 2; mt++) {
            #pragma unroll
            for (int p = 0; p < 2; p++) {
                MMA(acc[mt][2*p],   Ax[mt], Bf[p][0], Bf[p][1]);
                MMA(acc[mt][2*p+1], Ax[mt], Bf[p][2], Bf[p][3]);
            }
        }
    }
}

// ---------------------------------------------------------------------------
__global__ void prep_w(const float* __restrict__ w1,
                       const float* __restrict__ g1, const float* __restrict__ b1,
                       const float* __restrict__ m1, const float* __restrict__ v1,
                       const float* __restrict__ w2,
                       const float* __restrict__ g2, const float* __restrict__ b2,
                       const float* __restrict__ m2, const float* __restrict__ v2)
{
    int i = blockIdx.x * blockDim.x + threadIdx.x;
    const int W1E = CH1 * 256 * 128;  // 131072
    const int W2E = 2 * 256 * 128;    // 65536
    if (i < W1E) {
        int t = i >> 15, rem = i & 32767, o = rem >> 7, k = rem & 127;
        int c = t * 128 + k;
        float s = g1[o] * rsqrtf(v1[o] + 1e-5f);
        d_w1[i] = __half_as_ushort(__float2half_rn(w1[o * C0 + c + 3] * s));
    }
    int j = i - W1E;
    if (j >= 0 && j < W2E) {
        int t = j >> 15, rem = j & 32767, o = rem >> 7, k = rem & 127;
        float s = g2[o] * rsqrtf(v2[o] + 1e-5f);
        d_w2[j] = __half_as_ushort(__float2half_rn(w2[o * 256 + t * 128 + k] * s));
    }
    if (i < 256) {
        float s1 = g1[i] * rsqrtf(v1[i] + 1e-5f);
        d_wr4[i * 4 + 0] = w1[i * C0 + 0] * s1;
        d_wr4[i * 4 + 1] = w1[i * C0 + 1] * s1;
        d_wr4[i * 4 + 2] = w1[i * C0 + 2] * s1;
        d_wr4[i * 4 + 3] = b1[i] - m1[i] * s1;
        float s2 = g2[i] * rsqrtf(v2[i] + 1e-5f);
        d_bias2[i] = b2[i] - m2[i] * s2;
    }
}

__global__ void transpose_feat(const float* __restrict__ f)
{
    __shared__ float tile[32][33];
    int b  = blockIdx.z;
    int c0 = blockIdx.y * 32;
    int n0 = blockIdx.x * 32;
    int tx = threadIdx.x, ty = threadIdx.y;
    const float* src = f + (size_t)b * CIN * Nc;
    #pragma unroll
    for (int k = 0; k < 32; k += 8)
        tile[ty + k][tx] = src[(c0 + ty + k) * Nc + n0 + tx];
    __syncthreads();
    size_t base = (size_t)b * Nc * CIN;
    #pragma unroll
    for (int k = 0; k < 32; k += 8) {
        float v = tile[tx][ty + k];
        d_fh[base + (size_t)(n0 + ty + k) * CIN + c0 + tx] =
            __half_as_ushort(__float2half_rn(v));
    }
}

__global__ void cylinder_query(const float* __restrict__ xyz,
                               const float* __restrict__ rot)
{
    __shared__ int sidx[4][NS];
    int w    = threadIdx.x >> 5;
    int lane = threadIdx.x & 31;
    int p = blockIdx.x * 4 + w;
    int b = p >> 10, n = p & 1023;

    const float* X = xyz + (size_t)b * Nc * 3;
    float cx = X[n * 3 + 0], cy = X[n * 3 + 1], cz = X[n * 3 + 2];
    const float* R = rot + (size_t)p * 9;
    float r00 = R[0], r01 = R[1], r02 = R[2];
    float r10 = R[3], r11 = R[4], r12 = R[5];
    float r20 = R[6], r21 = R[7], r22 = R[8];
    const float R2 = RADIUSf * RADIUSf;

    int cnt = 0;
    for (int m0 = 0; m0 < Nc; m0 += 32) {
        int m = m0 + lane;
        float dx = X[m * 3 + 0] - cx;
        float dy = X[m * 3 + 1] - cy;
        float dz = X[m * 3 + 2] - cz;
        float xr = r00 * dx + r01 * dy + r02 * dz;
        float yr = r10 * dx + r11 * dy + r12 * dz;
        float zr = r20 * dx + r21 * dy + r22 * dz;
        bool mk = (yr * yr + zr * zr < R2) && (xr > HMINf) && (xr < HMAXf);
        unsigned bal = __ballot_sync(0xffffffffu, mk);
        int pre = __popc(bal & ((1u << lane) - 1u));
        int slot = cnt + pre;
        if (mk && slot < NS) sidx[w][slot] = m;
        cnt += __popc(bal);
        if (cnt >= NS) break;
    }
    __syncwarp();
    int c32 = cnt < NS ? cnt : NS;
    int pad = (cnt > 0) ? sidx[w][0] : 0;
    int j = (lane < c32) ? sidx[w][lane] : pad;

    d_idx[p * NS + lane] = j;
    float dx = X[j * 3 + 0] - cx;
    float dy = X[j * 3 + 1] - cy;
    float dz = X[j * 3 + 2] - cz;
    float inv = 1.0f / RADIUSf;
    d_rel[(p * NS + lane) * 3 + 0] = (dx * r00 + dy * r10 + dz * r20) * inv;
    d_rel[(p * NS + lane) * 3 + 1] = (dx * r01 + dy * r11 + dz * r21) * inv;
    d_rel[(p * NS + lane) * 3 + 2] = (dx * r02 + dy * r12 + dz * r22) * inv;
}

// ---------------------------------------------------------------------------
// f_gemm (R15 verbatim): F[p][o] = sum_c feat[p][c] * W1f[o][c].
// grid=128: CTA = (64 rows) x (128 cols), K=512. Warp tile 32x32.
// ---------------------------------------------------------------------------
__global__ void __launch_bounds__(256, 1)
f_gemm()
{
    extern __shared__ char smem[];
    uint32_t sb = s2u(smem);
    int tid  = threadIdx.x;
    int lane = tid & 31;
    int w    = tid >> 5;
    int mh2  = w >> 2;
    int nq   = w & 3;
    int p0   = (blockIdx.x >> 1) * 64;
    int nh   = blockIdx.x & 1;

    uint32_t a_off = (uint32_t)((mh2 * 32 + (lane & 15)) * KROWB + (lane >> 4) * 16);
    uint32_t w_off = (uint32_t)((nq * 32 + (lane & 7) + ((lane >> 4) << 3)) * KROWB
                                + ((lane >> 3) & 1) * 16);

    auto issue = [&](int t) {
        int buf = t & 1;
        #pragma unroll
        for (int it = 0; it < 4; it++) {
            int e = tid + it * 256;
            int r = e >> 4, q = e & 15;
            uint32_t dst = sb + FG_A1 + (uint32_t)(buf * FGABUF + r * KROWB + q * 16);
            const char* srcb = (const char*)d_fh + (size_t)(p0 + r) * 1024 + t * 256 + q * 16;
            cpa16(dst, srcb);
        }
        #pragma unroll
        for (int it = 0; it < 8; it++) {
            int e = tid + it * 256;
            int o = e >> 4, q = e & 15;
            uint32_t dst = sb + FG_W + (uint32_t)(buf * FGWBUF + o * KROWB + q * 16);
            const char* srcb = (const char*)d_w1 + (size_t)t * 65536
                             + (size_t)(nh * 128 + o) * 256 + q * 16;
            cpa16(dst, srcb);
        }
        CP_COMMIT();
    };

    float4 acc[2][4];
    #pragma unroll
    for (int mt = 0; mt < 2; mt++)
        #pragma unroll
        for (int nt = 0; nt < 4; nt++) acc[mt][nt] = make_float4(0.f, 0.f, 0.f, 0.f);

    issue(0);
    for (int t = 0; t < CH1; t++) {
        int buf = t & 1;
        CP_WAITG(0);
        __syncthreads();
        if (t + 1 < CH1) issue(t + 1);
        gemm_round32(acc,
            sb + FG_A1 + (uint32_t)(buf * FGABUF) + a_off,
            sb + FG_W  + (uint32_t)(buf * FGWBUF) + w_off);
    }

    #pragma unroll
    for (int mt = 0; mt < 2; mt++) {
        int row0 = mh2 * 32 + mt * 16 + (lane >> 2);
        #pragma unroll
        for (int nt = 0; nt < 4; nt++) {
            int cl = nq * 32 + nt * 8 + (lane & 3) * 2;
            float4 c = acc[mt][nt];
            uint32_t u0 = __half_as_ushort(__float2half_rn(c.x))
                        | ((uint32_t)__half_as_ushort(__float2half_rn(c.y)) << 16);
            uint32_t u1 = __half_as_ushort(__float2half_rn(c.z))
                        | ((uint32_t)__half_as_ushort(__float2half_rn(c.w)) << 16);
            *(uint32_t*)(d_F + (size_t)(p0 + row0) * 256 + nh * 128 + cl)     = u0;
            *(uint32_t*)(d_F + (size_t)(p0 + row0 + 8) * 256 + nh * 128 + cl) = u1;
        }
    }
}

// ---------------------------------------------------------------------------
// tc_mlp4 (persistent, grid=148): column-half pipelined iteration.
// ---------------------------------------------------------------------------
__global__ void __launch_bounds__(256, 1)
tc_mlp4(float* __restrict__ out)
{
    extern __shared__ char smem[];
    uint32_t sb = s2u(smem);
    int tid  = threadIdx.x;
    int lane = tid & 31;
    int w    = tid >> 5;
    int mh   = w >> 2;
    int nq   = w & 3;

    float4* wr4s  = (float4*)(smem + SM_WR);
    float* bias2s = (float*)(smem + SM_B2);

    wr4s[tid] = *(const float4*)(d_wr4 + tid * 4);
    bias2s[tid] = d_bias2[tid];

    // persistent W2 (one group)
    #pragma unroll
    for (int t = 0; t < 2; t++) {
        #pragma unroll
        for (int it = 0; it < 16; it++) {
            int e = tid + it * 256;
            int o = e >> 4, q = e & 15;
            uint32_t dst = sb + SM_W + (uint32_t)(t * WBUF + o * KROWB + q * 16);
            const char* srcb = (const char*)d_w2 + (size_t)t * 65536 + o * 256 + q * 16;
            cpa16(dst, srcb);
        }
    }
    CP_COMMIT();

    const char* Fb = (const char*)d_F;
    uint32_t a2_off = (uint32_t)((mh * 64 + (lane & 15)) * A2ROWB + (lane >> 4) * 16);
    uint32_t w_off  = (uint32_t)((nq * 64 + (lane & 7) + ((lane >> 4) << 3)) * KROWB
                                 + ((lane >> 3) & 1) * 16);

    // meta: plain LDG/STS into double buffer
    auto load_meta = [&](int b, int mb) {
        if (tid < 128) {
            int*    lx = (int*)(smem + SM_META + mb * MB2SZ);
            float4* rl = (float4*)(smem + SM_META + mb * MB2SZ + 512);
            lx[tid] = d_idx[b * 128 + tid];
            rl[tid] = make_float4(d_rel[(b * 128 + tid) * 3 + 0],
                                  d_rel[(b * 128 + tid) * 3 + 1],
                                  d_rel[(b * 128 + tid) * 3 + 2], 0.f);
        }
    };
    // gather one COLUMN half (128 rows x 256B) from F by idx; one commit group
    auto issue_gather_half = [&](int b, int mb, int half) {
        const int* lx = (const int*)(smem + SM_META + mb * MB2SZ);
        #pragma unroll
        for (int it = 0; it < 8; it++) {
            int e = tid + it * 256;
            int r = e >> 4, q = e & 15;
            uint32_t dst = sb + SM_A2 + (uint32_t)(r * A2ROWB + half * 256 + q * 16);
            const char* srcb = Fb + (size_t)((b >> 8) * 1024 + lx[r]) * 512
                                  + half * 256 + q * 16;
            cpa16(dst, srcb);
        }
        CP_COMMIT();
    };
    // rank-3 rel update + bias + relu on cols [half*128, half*128+128)
    auto update_half = [&](int half, int mb) {
        int cp_ = tid & 63;                // col pair within half
        int rq  = tid >> 6;                // row quarter (32 rows)
        int c0  = half * 128 + cp_ * 2;
        float4 wa  = wr4s[c0];
        float4 wb4 = wr4s[c0 + 1];
        const float4* rl = (const float4*)(smem + SM_META + mb * MB2SZ + 512);
        char* base = smem + SM_A2 + c0 * 2;
        #pragma unroll 4
        for (int i = 0; i < 32; i++) {
            int r = rq * 32 + i;
            uint32_t* addr = (uint32_t*)(base + r * A2ROWB);
            uint32_t u = *addr;
            float f0 = __half2float(__ushort_as_half((unsigned short)(u & 0xffff)));
            float f1 = __half2float(__ushort_as_half((unsigned short)(u >> 16)));
            float4 r4 = rl[r];
            float y0 = f0 + r4.x * wa.x  + r4.y * wa.y  + r4.z * wa.z  + wa.w;
            float y1 = f1 + r4.x * wb4.x + r4.y * wb4.y + r4.z * wb4.z + wb4.w;
            unsigned short h0 = __half_as_ushort(__float2half_rn(fmaxf(y0, 0.f)));
            unsigned short h1 = __half_as_ushort(__float2half_rn(fmaxf(y1, 0.f)));
            *addr = h0 | ((uint32_t)h1 << 16);
        }
    };

    // prologue
    int blk = blockIdx.x;                  // 148 < 1024 always
    load_meta(blk, 0);
    __syncthreads();                       // meta buf0 visible
    issue_gather_half(blk, 0, 0);          // g0(blk)
    issue_gather_half(blk, 0, 1);          // g1(blk)

    int par = 0;
    for (; blk < 1024; blk += 148, par ^= 1) {
        int nblk = blk + 148;
        bool more = (nblk < 1024);
        if (more) load_meta(nblk, par ^ 1);   // plain LDG/STS, other buffer

        CP_WAITG(1);                       // g0 landed (+W2 on first iter)
        __syncthreads();                   // also publishes meta(par^1) writes
        update_half(0, par);
        __syncthreads();

        float4 acc[4][8];
        #pragma unroll
        for (int mt = 0; mt < 4; mt++)
            #pragma unroll
            for (int nt = 0; nt < 8; nt++) acc[mt][nt] = make_float4(0.f, 0.f, 0.f, 0.f);

        gemm_round<A2ROWB>(acc, sb + SM_A2 + a2_off, sb + SM_W + w_off);   // round 0
        __syncthreads();                   // cols 0-127 reads done
        if (more) issue_gather_half(nblk, par ^ 1, 0);   // next g0 -> cols 0-127

        if (more) { CP_WAITG(1); } else { CP_WAITG(0); } // g1(blk) landed
        __syncthreads();
        update_half(1, par);
        __syncthreads();

        gemm_round<A2ROWB>(acc, sb + SM_A2 + a2_off + 256, sb + SM_W + WBUF + w_off); // round 1
        __syncthreads();                   // cols 128-255 reads done
        if (more) issue_gather_half(nblk, par ^ 1, 1);   // next g1

        // maxpool over 32 samples + bias + relu, store
        int bb    = blk >> 8;
        int nbase = (blk & 255) * 4;
        #pragma unroll
        for (int nt = 0; nt < 8; nt++) {
            float4 c0 = acc[0][nt], c1 = acc[1][nt], c2 = acc[2][nt], c3 = acc[3][nt];
            float p0a = fmaxf(fmaxf(c0.x, c0.z), fmaxf(c1.x, c1.z));
            float p0b = fmaxf(fmaxf(c0.y, c0.w), fmaxf(c1.y, c1.w));
            float p1a = fmaxf(fmaxf(c2.x, c2.z), fmaxf(c3.x, c3.z));
            float p1b = fmaxf(fmaxf(c2.y, c2.w), fmaxf(c3.y, c3.w));
            #pragma unroll
            for (int off = 4; off < 32; off <<= 1) {
                p0a = fmaxf(p0a, __shfl_xor_sync(0xffffffffu, p0a, off));
                p0b = fmaxf(p0b, __shfl_xor_sync(0xffffffffu, p0b, off));
                p1a = fmaxf(p1a, __shfl_xor_sync(0xffffffffu, p1a, off));
                p1b = fmaxf(p1b, __shfl_xor_sync(0xffffffffu, p1b, off));
            }
            if (lane < 4) {
                int col0 = nq * 64 + nt * 8 + lane * 2;
                int n0 = nbase + mh * 2;
                float bA = bias2s[col0], bB = bias2s[col0 + 1];
                out[((size_t)bb * 256 + col0)     * 1024 + n0]     = fmaxf(p0a + bA, 0.f);
                out[((size_t)bb * 256 + col0 + 1) * 1024 + n0]     = fmaxf(p0b + bB, 0.f);
                out[((size_t)bb * 256 + col0)     * 1024 + n0 + 1] = fmaxf(p1a + bA, 0.f);
                out[((size_t)bb * 256 + col0 + 1) * 1024 + n0 + 1] = fmaxf(p1b + bB, 0.f);
            }
        }
    }
}

// ---------------------------------------------------------------------------
extern "C" void kernel_launch(void* const* d_in, const int* in_sizes, int n_in,
                              void* d_out, int out_size)
{
    const float* xyz  = (const float*)d_in[0];
    const float* feat = (const float*)d_in[1];
    const float* rot  = (const float*)d_in[2];
    const float* w1   = (const float*)d_in[3];
    const float* g1   = (const float*)d_in[4];
    const float* b1   = (const float*)d_in[5];
    const float* m1   = (const float*)d_in[6];
    const float* v1   = (const float*)d_in[7];
    const float* w2   = (const float*)d_in[8];
    const float* g2   = (const float*)d_in[9];
    const float* b2   = (const float*)d_in[10];
    const float* m2   = (const float*)d_in[11];
    const float* v2   = (const float*)d_in[12];
    float* out = (float*)d_out;

    cudaFuncSetAttribute(f_gemm,  cudaFuncAttributeMaxDynamicSharedMemorySize, FG_TOTAL);
    cudaFuncSetAttribute(tc_mlp4, cudaFuncAttributeMaxDynamicSharedMemorySize, SM_TOTAL);

    int prep_total = (CH1 + 2) * 256 * 128;      // 196608
    prep_w<<<(prep_total + 255) / 256, 256>>>(w1, g1, b1, m1, v1,
                                              w2, g2, b2, m2, v2);
    transpose_feat<<<dim3(Nc / 32, CIN / 32, Bc), dim3(32, 8)>>>(feat);
    cylinder_query<<<(Bc * Nc) / 4, 128>>>(xyz, rot);
    f_gemm<<<Bc * Nc / 32, 256, FG_TOTAL>>>();
    tc_mlp4<<<148, 256, SM_TOTAL>>>(out);
}

// round 17
// speedup vs baseline: 1.0271x; 1.0271x over previous
#include <cuda_runtime.h>
#include <cuda_fp16.h>
#include <cstdint>

// ---------------------------------------------------------------------------
// CloudCrop R17: R15 (measured 105.2us) with the three prologue kernels
// (prep_w / transpose_feat / cylinder_query) fused into ONE kernel with
// blockIdx-range work split (they are mutually independent; no barriers).
// f_gemm and tc_mlp3 are R15 verbatim.
// ---------------------------------------------------------------------------

#define Bc 4
#define Nc 1024
#define NS 32
#define CIN 512
#define C0 515
#define RADIUSf 0.05f
#define HMINf (-0.02f)
#define HMAXf 0.04f

#define KROWB 272             // GEMM tile row bytes (128 fp16 + 16B pad)
#define CH1 4                 // f_gemm K chunks (K=512)
#define A2ROWB 528            // A2 row bytes (256 fp16 + 16B pad)
#define FGABUF 17408          // f_gemm A tile: 64 rows * 272B
#define FGWBUF 34816          // f_gemm W tile: 128 rows * 272B
#define WBUF  69632           // tc_mlp W tile: 256 rows * 272B

// f_gemm smem
#define FG_A1    0
#define FG_W     34816
#define FG_TOTAL 104448

// tc_mlp3 smem (R15 verbatim)
#define SM_A2    0            // 128 x 528 = 67584
#define SM_W     67584        // 2 x 69632 -> 206848 (persistent W2)
#define SM_WR    206848       // w1rel+bias1 [256][4] f32 = 4096
#define SM_B2    210944       // bias2 f32 = 1024
#define SM_REL   211968       // rel [128][4] f32 = 2048
#define SM_LIDX  214016       // 128 ints = 512
#define SM_TOTAL 214528

// fused_pre grid split
#define PRE_P    772          // prep: 772*256 = 197632 elements
#define PRE_T    2048         // transpose: 4 * 16 * 32 tiles of 32x32
#define PRE_C    512          // cylinder: 512 CTAs * 8 points
#define PRE_GRID (PRE_P + PRE_T + PRE_C)

// __device__ scratch (allocation-free), 16B-aligned
__device__ __align__(16) unsigned short d_fh[Bc * Nc * CIN];    // feat fp16 [p][c]
__device__ __align__(16) unsigned short d_F[Bc * Nc * 256];     // W1f·feat fp16 [p][o]
__device__ __align__(16) int            d_idx[Bc * Nc * NS];
__device__ __align__(16) float          d_rel[Bc * Nc * NS * 3];
__device__ __align__(16) unsigned short d_w1[CH1 * 256 * 128];  // [t][o][128] fp16
__device__ __align__(16) unsigned short d_w2[2 * 256 * 128];
__device__ __align__(16) float          d_wr4[256 * 4];         // {wr0,wr1,wr2,bias1}
__device__ __align__(16) float          d_bias2[256];

__device__ __forceinline__ uint32_t s2u(const void* p) {
    uint32_t a;
    asm("{ .reg .u64 t; cvta.to.shared.u64 t, %1; cvt.u32.u64 %0, t; }" : "=r"(a) : "l"(p));
    return a;
}
__device__ __forceinline__ void cpa16(uint32_t dst, const void* src) {
    asm volatile("cp.async.cg.shared.global [%0], [%1], 16;" :: "r"(dst), "l"(src));
}
#define CP_COMMIT()  asm volatile("cp.async.commit_group;" ::: "memory")
#define CP_WAITG(n)  asm volatile("cp.async.wait_group %0;" :: "n"(n) : "memory")

__device__ __forceinline__ void ldsm4(uint32_t& r0, uint32_t& r1, uint32_t& r2, uint32_t& r3,
                                      uint32_t addr) {
    asm volatile("ldmatrix.sync.aligned.m8n8.x4.shared.b16 {%0,%1,%2,%3}, [%4];"
                 : "=r"(r0), "=r"(r1), "=r"(r2), "=r"(r3) : "r"(addr));
}
#define MMA(d, A, b0r, b1r) \
    asm volatile("mma.sync.aligned.m16n8k16.row.col.f32.f16.f16.f32 " \
                 "{%0,%1,%2,%3},{%4,%5,%6,%7},{%8,%9},{%0,%1,%2,%3};" \
                 : "+f"((d).x), "+f"((d).y), "+f"((d).z), "+f"((d).w) \
                 : "r"((A)[0]), "r"((A)[1]), "r"((A)[2]), "r"((A)[3]), \
                   "r"(b0r), "r"(b1r))

// K=128 round, 64x64 warp tile (tc_mlp3)
template<int AROW>
__device__ __forceinline__ void gemm_round(float4 (&acc)[4][8], uint32_t a, uint32_t wb)
{
    #pragma unroll
    for (int kk = 0; kk < 8; kk++) {
        uint32_t Ax[4][4], Bf[4][4];
        uint32_t ak = a + kk * 32, wk = wb + kk * 32;
        #pragma unroll
        for (int mt = 0; mt < 4; mt++)
            ldsm4(Ax[mt][0], Ax[mt][1], Ax[mt][2], Ax[mt][3], ak + mt * 16 * AROW);
        #pragma unroll
        for (int p = 0; p < 4; p++)
            ldsm4(Bf[p][0], Bf[p][1], Bf[p][2], Bf[p][3], wk + p * 16 * KROWB);
        #pragma unroll
        for (int mt = 0; mt < 4; mt++) {
            #pragma unroll
            for (int p = 0; p < 4; p++) {
                MMA(acc[mt][2*p],   Ax[mt], Bf[p][0], Bf[p][1]);
                MMA(acc[mt][2*p+1], Ax[mt], Bf[p][2], Bf[p][3]);
            }
        }
    }
}

// K=128 round, 32x32 warp tile (f_gemm)
__device__ __forceinline__ void gemm_round32(float4 (&acc)[2][4], uint32_t a, uint32_t wb)
{
    #pragma unroll
    for (int kk = 0; kk < 8; kk++) {
        uint32_t Ax[2][4], Bf[2][4];
        uint32_t ak = a + kk * 32, wk = wb + kk * 32;
        #pragma unroll
        for (int mt = 0; mt < 2; mt++)
            ldsm4(Ax[mt][0], Ax[mt][1], Ax[mt][2], Ax[mt][3], ak + mt * 16 * KROWB);
        #pragma unroll
        for (int p = 0; p < 2; p++)
            ldsm4(Bf[p][0], Bf[p][1], Bf[p][2], Bf[p][3], wk + p * 16 * KROWB);
        #pragma unroll
        for (int mt = 0; mt < 2; mt++) {
            #pragma unroll
            for (int p = 0; p < 2; p++) {
                MMA(acc[mt][2*p],   Ax[mt], Bf[p][0], Bf[p][1]);
                MMA(acc[mt][2*p+1], Ax[mt], Bf[p][2], Bf[p][3]);
            }
        }
    }
}

// ---------------------------------------------------------------------------
// fused_pre: three independent jobs split by blockIdx.
//   [0, PRE_P)            : weight prep (BN fold -> fp16 chunks + wr4/bias2)
//   [PRE_P, PRE_P+PRE_T)  : transpose [B,512,N] -> point-major fp16 [p][512]
//   [PRE_P+PRE_T, ...)    : cylinder query, 8 points per CTA
// ---------------------------------------------------------------------------
__global__ void __launch_bounds__(256)
fused_pre(const float* __restrict__ xyz,  const float* __restrict__ feat,
          const float* __restrict__ rot,
          const float* __restrict__ w1,
          const float* __restrict__ g1, const float* __restrict__ b1,
          const float* __restrict__ m1, const float* __restrict__ v1,
          const float* __restrict__ w2,
          const float* __restrict__ g2, const float* __restrict__ b2,
          const float* __restrict__ m2, const float* __restrict__ v2)
{
    __shared__ float tile[32][33];
    __shared__ int   sidx[8][NS];
    int bid = blockIdx.x;
    int tid = threadIdx.x;

    if (bid < PRE_P) {
        // ---------------- weight prep ----------------
        int i = bid * 256 + tid;
        const int W1E = CH1 * 256 * 128;  // 131072
        const int W2E = 2 * 256 * 128;    // 65536
        if (i < W1E) {
            int t = i >> 15, rem = i & 32767, o = rem >> 7, k = rem & 127;
            int c = t * 128 + k;
            float s = g1[o] * rsqrtf(v1[o] + 1e-5f);
            d_w1[i] = __half_as_ushort(__float2half_rn(w1[o * C0 + c + 3] * s));
        }
        int j = i - W1E;
        if (j >= 0 && j < W2E) {
            int t = j >> 15, rem = j & 32767, o = rem >> 7, k = rem & 127;
            float s = g2[o] * rsqrtf(v2[o] + 1e-5f);
            d_w2[j] = __half_as_ushort(__float2half_rn(w2[o * 256 + t * 128 + k] * s));
        }
        if (i < 256) {
            float s1 = g1[i] * rsqrtf(v1[i] + 1e-5f);
            d_wr4[i * 4 + 0] = w1[i * C0 + 0] * s1;
            d_wr4[i * 4 + 1] = w1[i * C0 + 1] * s1;
            d_wr4[i * 4 + 2] = w1[i * C0 + 2] * s1;
            d_wr4[i * 4 + 3] = b1[i] - m1[i] * s1;
            float s2 = g2[i] * rsqrtf(v2[i] + 1e-5f);
            d_bias2[i] = b2[i] - m2[i] * s2;
        }
    } else if (bid < PRE_P + PRE_T) {
        // ---------------- transpose tile ----------------
        int tt = bid - PRE_P;              // 0..2047
        int b  = tt >> 9;                  // 512 tiles per batch (16 x 32)
        int rem = tt & 511;
        int c0 = (rem >> 5) * 32;          // 16 channel groups
        int n0 = (rem & 31) * 32;          // 32 point groups
        int tx = tid & 31, ty = tid >> 5;  // (32, 8)
        const float* src = feat + (size_t)b * CIN * Nc;
        #pragma unroll
        for (int k = 0; k < 32; k += 8)
            tile[ty + k][tx] = src[(c0 + ty + k) * Nc + n0 + tx];
        __syncthreads();
        size_t base = (size_t)b * Nc * CIN;
        #pragma unroll
        for (int k = 0; k < 32; k += 8) {
            float v = tile[tx][ty + k];
            d_fh[base + (size_t)(n0 + ty + k) * CIN + c0 + tx] =
                __half_as_ushort(__float2half_rn(v));
        }
    } else {
        // ---------------- cylinder query (8 points / CTA) ----------------
        int w    = tid >> 5;
        int lane = tid & 31;
        int p = (bid - PRE_P - PRE_T) * 8 + w;
        int b = p >> 10, n = p & 1023;

        const float* X = xyz + (size_t)b * Nc * 3;
        float cx = X[n * 3 + 0], cy = X[n * 3 + 1], cz = X[n * 3 + 2];
        const float* R = rot + (size_t)p * 9;
        float r00 = R[0], r01 = R[1], r02 = R[2];
        float r10 = R[3], r11 = R[4], r12 = R[5];
        float r20 = R[6], r21 = R[7], r22 = R[8];
        const float R2 = RADIUSf * RADIUSf;

        int cnt = 0;
        for (int m0 = 0; m0 < Nc; m0 += 32) {
            int m = m0 + lane;
            float dx = X[m * 3 + 0] - cx;
            float dy = X[m * 3 + 1] - cy;
            float dz = X[m * 3 + 2] - cz;
            float xr = r00 * dx + r01 * dy + r02 * dz;
            float yr = r10 * dx + r11 * dy + r12 * dz;
            float zr = r20 * dx + r21 * dy + r22 * dz;
            bool mk = (yr * yr + zr * zr < R2) && (xr > HMINf) && (xr < HMAXf);
            unsigned bal = __ballot_sync(0xffffffffu, mk);
            int pre = __popc(bal & ((1u << lane) - 1u));
            int slot = cnt + pre;
            if (mk && slot < NS) sidx[w][slot] = m;
            cnt += __popc(bal);
            if (cnt >= NS) break;
        }
        __syncwarp();
        int c32 = cnt < NS ? cnt : NS;
        int pad = (cnt > 0) ? sidx[w][0] : 0;
        int j = (lane < c32) ? sidx[w][lane] : pad;

        d_idx[p * NS + lane] = j;
        float dx = X[j * 3 + 0] - cx;
        float dy = X[j * 3 + 1] - cy;
        float dz = X[j * 3 + 2] - cz;
        float inv = 1.0f / RADIUSf;
        d_rel[(p * NS + lane) * 3 + 0] = (dx * r00 + dy * r10 + dz * r20) * inv;
        d_rel[(p * NS + lane) * 3 + 1] = (dx * r01 + dy * r11 + dz * r21) * inv;
        d_rel[(p * NS + lane) * 3 + 2] = (dx * r02 + dy * r12 + dz * r22) * inv;
    }
}

// ---------------------------------------------------------------------------
// f_gemm (R15 verbatim): F[p][o] = sum_c feat[p][c] * W1f[o][c].
// grid=128: CTA = (64 rows) x (128 cols), K=512. Warp tile 32x32.
// ---------------------------------------------------------------------------
__global__ void __launch_bounds__(256, 1)
f_gemm()
{
    extern __shared__ char smem[];
    uint32_t sb = s2u(smem);
    int tid  = threadIdx.x;
    int lane = tid & 31;
    int w    = tid >> 5;
    int mh2  = w >> 2;
    int nq   = w & 3;
    int p0   = (blockIdx.x >> 1) * 64;
    int nh   = blockIdx.x & 1;

    uint32_t a_off = (uint32_t)((mh2 * 32 + (lane & 15)) * KROWB + (lane >> 4) * 16);
    uint32_t w_off = (uint32_t)((nq * 32 + (lane & 7) + ((lane >> 4) << 3)) * KROWB
                                + ((lane >> 3) & 1) * 16);

    auto issue = [&](int t) {
        int buf = t & 1;
        #pragma unroll
        for (int it = 0; it < 4; it++) {
            int e = tid + it * 256;
            int r = e >> 4, q = e & 15;
            uint32_t dst = sb + FG_A1 + (uint32_t)(buf * FGABUF + r * KROWB + q * 16);
            const char* srcb = (const char*)d_fh + (size_t)(p0 + r) * 1024 + t * 256 + q * 16;
            cpa16(dst, srcb);
        }
        #pragma unroll
        for (int it = 0; it < 8; it++) {
            int e = tid + it * 256;
            int o = e >> 4, q = e & 15;
            uint32_t dst = sb + FG_W + (uint32_t)(buf * FGWBUF + o * KROWB + q * 16);
            const char* srcb = (const char*)d_w1 + (size_t)t * 65536
                             + (size_t)(nh * 128 + o) * 256 + q * 16;
            cpa16(dst, srcb);
        }
        CP_COMMIT();
    };

    float4 acc[2][4];
    #pragma unroll
    for (int mt = 0; mt < 2; mt++)
        #pragma unroll
        for (int nt = 0; nt < 4; nt++) acc[mt][nt] = make_float4(0.f, 0.f, 0.f, 0.f);

    issue(0);
    for (int t = 0; t < CH1; t++) {
        int buf = t & 1;
        CP_WAITG(0);
        __syncthreads();
        if (t + 1 < CH1) issue(t + 1);
        gemm_round32(acc,
            sb + FG_A1 + (uint32_t)(buf * FGABUF) + a_off,
            sb + FG_W  + (uint32_t)(buf * FGWBUF) + w_off);
    }

    #pragma unroll
    for (int mt = 0; mt < 2; mt++) {
        int row0 = mh2 * 32 + mt * 16 + (lane >> 2);
        #pragma unroll
        for (int nt = 0; nt < 4; nt++) {
            int cl = nq * 32 + nt * 8 + (lane & 3) * 2;
            float4 c = acc[mt][nt];
            uint32_t u0 = __half_as_ushort(__float2half_rn(c.x))
                        | ((uint32_t)__half_as_ushort(__float2half_rn(c.y)) << 16);
            uint32_t u1 = __half_as_ushort(__float2half_rn(c.z))
                        | ((uint32_t)__half_as_ushort(__float2half_rn(c.w)) << 16);
            *(uint32_t*)(d_F + (size_t)(p0 + row0) * 256 + nh * 128 + cl)     = u0;
            *(uint32_t*)(d_F + (size_t)(p0 + row0 + 8) * 256 + nh * 128 + cl) = u1;
        }
    }
}

// ---------------------------------------------------------------------------
// tc_mlp3 (persistent, grid=148) — R15 VERBATIM.
// ---------------------------------------------------------------------------
__global__ void __launch_bounds__(256, 1)
tc_mlp3(float* __restrict__ out)
{
    extern __shared__ char smem[];
    uint32_t sb = s2u(smem);
    int tid  = threadIdx.x;
    int lane = tid & 31;
    int w    = tid >> 5;
    int mh   = w >> 2;
    int nq   = w & 3;

    float* wr4s   = (float*)(smem + SM_WR);
    float* bias2s = (float*)(smem + SM_B2);
    float* rels   = (float*)(smem + SM_REL);
    int*   lidx   = (int*)(smem + SM_LIDX);

    *(float4*)(wr4s + tid * 4) = *(const float4*)(d_wr4 + tid * 4);
    bias2s[tid] = d_bias2[tid];

    // persistent W2: both K chunks, loaded once
    #pragma unroll
    for (int t = 0; t < 2; t++) {
        #pragma unroll
        for (int it = 0; it < 16; it++) {
            int e = tid + it * 256;
            int o = e >> 4, q = e & 15;
            uint32_t dst = sb + SM_W + (uint32_t)(t * WBUF + o * KROWB + q * 16);
            const char* srcb = (const char*)d_w2 + (size_t)t * 65536 + o * 256 + q * 16;
            cpa16(dst, srcb);
        }
        CP_COMMIT();
    }

    const char* Fb = (const char*)d_F;
    uint32_t a2_off = (uint32_t)((mh * 64 + (lane & 15)) * A2ROWB + (lane >> 4) * 16);
    uint32_t w_off  = (uint32_t)((nq * 64 + (lane & 7) + ((lane >> 4) << 3)) * KROWB
                                 + ((lane >> 3) & 1) * 16);

    auto load_meta = [&](int b) {
        if (tid < 128) {
            lidx[tid] = d_idx[b * 128 + tid];
            rels[tid * 4 + 0] = d_rel[(b * 128 + tid) * 3 + 0];
            rels[tid * 4 + 1] = d_rel[(b * 128 + tid) * 3 + 1];
            rels[tid * 4 + 2] = d_rel[(b * 128 + tid) * 3 + 2];
            rels[tid * 4 + 3] = 0.f;
        }
    };
    auto issue_gather = [&](int b) {
        #pragma unroll
        for (int half = 0; half < 2; half++) {
            #pragma unroll
            for (int it = 0; it < 8; it++) {
                int e = tid + it * 256;
                int r = e >> 4, q = e & 15;
                uint32_t dst = sb + SM_A2 + (uint32_t)(r * A2ROWB + half * 256 + q * 16);
                const char* srcb = Fb + (size_t)((b >> 8) * 1024 + lidx[r]) * 512
                                      + half * 256 + q * 16;
                cpa16(dst, srcb);
            }
        }
        CP_COMMIT();
    };

    int blk = blockIdx.x;
    if (blk < 1024) {
        load_meta(blk);
        __syncthreads();
        issue_gather(blk);
    }

    for (; blk < 1024; blk += gridDim.x) {
        CP_WAITG(0);               // gather landed (first iter: + W2)
        __syncthreads();

        // rank-3 rel update + bias + relu, in place on A2
        {
            int tp = tid & 127;
            int rh = tid >> 7;
            int c0 = tp * 2;
            float4 wa  = *(float4*)(wr4s + c0 * 4);
            float4 wb4 = *(float4*)(wr4s + (c0 + 1) * 4);
            char* base = smem + SM_A2 + c0 * 2;
            #pragma unroll 4
            for (int i = 0; i < 64; i++) {
                int r = rh * 64 + i;
                uint32_t* addr = (uint32_t*)(base + r * A2ROWB);
                uint32_t u = *addr;
                float f0 = __half2float(__ushort_as_half((unsigned short)(u & 0xffff)));
                float f1 = __half2float(__ushort_as_half((unsigned short)(u >> 16)));
                float4 r4 = *(float4*)(rels + r * 4);
                float y0 = f0 + r4.x * wa.x  + r4.y * wa.y  + r4.z * wa.z  + wa.w;
                float y1 = f1 + r4.x * wb4.x + r4.y * wb4.y + r4.z * wb4.z + wb4.w;
                unsigned short h0 = __half_as_ushort(__float2half_rn(fmaxf(y0, 0.f)));
                unsigned short h1 = __half_as_ushort(__float2half_rn(fmaxf(y1, 0.f)));
                *addr = h0 | ((uint32_t)h1 << 16);
            }
        }
        __syncthreads();

        float4 acc[4][8];
        #pragma unroll
        for (int mt = 0; mt < 4; mt++)
            #pragma unroll
            for (int nt = 0; nt < 8; nt++) acc[mt][nt] = make_float4(0.f, 0.f, 0.f, 0.f);

        gemm_round<A2ROWB>(acc, sb + SM_A2 + a2_off,        sb + SM_W + w_off);
        gemm_round<A2ROWB>(acc, sb + SM_A2 + a2_off + 256,  sb + SM_W + WBUF + w_off);

        __syncthreads();           // all warps done reading A2/rels

        int nblk = blk + gridDim.x;
        if (nblk < 1024) {         // prefetch next block's gather behind maxpool
            load_meta(nblk);
            __syncthreads();
            issue_gather(nblk);
        }

        // maxpool over 32 samples + bias + relu, store
        int bb    = blk >> 8;
        int nbase = (blk & 255) * 4;
        #pragma unroll
        for (int nt = 0; nt < 8; nt++) {
            float4 c0 = acc[0][nt], c1 = acc[1][nt], c2 = acc[2][nt], c3 = acc[3][nt];
            float p0a = fmaxf(fmaxf(c0.x, c0.z), fmaxf(c1.x, c1.z));
            float p0b = fmaxf(fmaxf(c0.y, c0.w), fmaxf(c1.y, c1.w));
            float p1a = fmaxf(fmaxf(c2.x, c2.z), fmaxf(c3.x, c3.z));
            float p1b = fmaxf(fmaxf(c2.y, c2.w), fmaxf(c3.y, c3.w));
            #pragma unroll
            for (int off = 4; off < 32; off <<= 1) {
                p0a = fmaxf(p0a, __shfl_xor_sync(0xffffffffu, p0a, off));
                p0b = fmaxf(p0b, __shfl_xor_sync(0xffffffffu, p0b, off));
                p1a = fmaxf(p1a, __shfl_xor_sync(0xffffffffu, p1a, off));
                p1b = fmaxf(p1b, __shfl_xor_sync(0xffffffffu, p1b, off));
            }
            if (lane < 4) {
                int col0 = nq * 64 + nt * 8 + lane * 2;
                int n0 = nbase + mh * 2;
                float bA = bias2s[col0], bB = bias2s[col0 + 1];
                out[((size_t)bb * 256 + col0)     * 1024 + n0]     = fmaxf(p0a + bA, 0.f);
                out[((size_t)bb * 256 + col0 + 1) * 1024 + n0]     = fmaxf(p0b + bB, 0.f);
                out[((size_t)bb * 256 + col0)     * 1024 + n0 + 1] = fmaxf(p1a + bA, 0.f);
                out[((size_t)bb * 256 + col0 + 1) * 1024 + n0 + 1] = fmaxf(p1b + bB, 0.f);
            }
        }
    }
}

// ---------------------------------------------------------------------------
extern "C" void kernel_launch(void* const* d_in, const int* in_sizes, int n_in,
                              void* d_out, int out_size)
{
    const float* xyz  = (const float*)d_in[0];
    const float* feat = (const float*)d_in[1];
    const float* rot  = (const float*)d_in[2];
    const float* w1   = (const float*)d_in[3];
    const float* g1   = (const float*)d_in[4];
    const float* b1   = (const float*)d_in[5];
    const float* m1   = (const float*)d_in[6];
    const float* v1   = (const float*)d_in[7];
    const float* w2   = (const float*)d_in[8];
    const float* g2   = (const float*)d_in[9];
    const float* b2   = (const float*)d_in[10];
    const float* m2   = (const float*)d_in[11];
    const float* v2   = (const float*)d_in[12];
    float* out = (float*)d_out;

    cudaFuncSetAttribute(f_gemm,  cudaFuncAttributeMaxDynamicSharedMemorySize, FG_TOTAL);
    cudaFuncSetAttribute(tc_mlp3, cudaFuncAttributeMaxDynamicSharedMemorySize, SM_TOTAL);

    fused_pre<<<PRE_GRID, 256>>>(xyz, feat, rot, w1, g1, b1, m1, v1,
                                 w2, g2, b2, m2, v2);
    f_gemm<<<Bc * Nc / 32, 256, FG_TOTAL>>>();
    tc_mlp3<<<148, 256, SM_TOTAL>>>(out);
}